// round 14
// baseline (speedup 1.0000x reference)
#include <cuda_runtime.h>
#include <cuda_fp16.h>
#include <cstdint>

// ---------------- Problem constants ----------------
#define T_SEQ   2048
#define NEMBD   2048
#define NHEAD   16
#define KVLOW   512
#define QLOW    1024
#define ROPEHS  64
#define QKHS    576
#define LATD    1600
#define QTOT    9216
#define YTOT    8192
#define NPAD1   1664   // 1600 padded up to 13*128

typedef __half h16;

// ---------------- Scratch (device globals; no allocations allowed) ----------------
__device__ float g_lat[(size_t)T_SEQ * LATD];
__device__ float g_qbuf[(size_t)T_SEQ * QTOT];
__device__ float g_scores[(size_t)NHEAD * T_SEQ * T_SEQ];

__device__ h16 g_xh[(size_t)T_SEQ * NEMBD];
__device__ h16 g_wqkvT[(size_t)NPAD1 * NEMBD];
__device__ h16 g_cqh[(size_t)T_SEQ * QLOW];
__device__ h16 g_wqdecT[(size_t)QTOT * QLOW];
__device__ h16 g_qh[(size_t)T_SEQ * QTOT];
__device__ h16 g_kh[(size_t)T_SEQ * QKHS];
__device__ h16 g_vT[(size_t)KVLOW * T_SEQ];
__device__ h16 g_attnh[(size_t)NHEAD * T_SEQ * T_SEQ];
__device__ h16 g_yh[(size_t)T_SEQ * YTOT];
__device__ h16 g_woutT[(size_t)NEMBD * YTOT];

// int8 quantized operands (value ~ scale[r] * (q1 + q2/128))
__device__ int8_t g_xq1[(size_t)T_SEQ * NEMBD];
__device__ int8_t g_xq2[(size_t)T_SEQ * NEMBD];
__device__ float  g_sx[T_SEQ];
__device__ int8_t g_wkq1[(size_t)NPAD1 * NEMBD];
__device__ int8_t g_wkq2[(size_t)NPAD1 * NEMBD];
__device__ float  g_swk[NPAD1];
__device__ int8_t g_cqq1[(size_t)T_SEQ * QLOW];
__device__ int8_t g_cqq2[(size_t)T_SEQ * QLOW];
__device__ float  g_scq[T_SEQ];
__device__ int8_t g_wdq1[(size_t)QTOT * QLOW];
__device__ int8_t g_wdq2[(size_t)QTOT * QLOW];
__device__ float  g_swd[QTOT];
__device__ int8_t g_yq1[(size_t)T_SEQ * YTOT];
__device__ int8_t g_yq2[(size_t)T_SEQ * YTOT];
__device__ float  g_sy[T_SEQ];
__device__ int8_t g_woq1[(size_t)NEMBD * YTOT];
__device__ int8_t g_woq2[(size_t)NEMBD * YTOT];
__device__ float  g_swo[NEMBD];

// ---------------- helpers ----------------
__device__ __forceinline__ uint32_t smem_u32(const void* p) {
    uint32_t a;
    asm("{ .reg .u64 t; cvta.to.shared.u64 t, %1; cvt.u32.u64 %0, t; }" : "=r"(a) : "l"(p));
    return a;
}

#define CPA(dst, src) \
    asm volatile("cp.async.cg.shared.global [%0], [%1], 16;\n" :: "r"(dst), "l"(src))
#define CP_COMMIT() asm volatile("cp.async.commit_group;\n" ::: "memory")
#define CP_WAIT(N)  asm volatile("cp.async.wait_group %0;\n" :: "n"(N) : "memory")

#define LDSM4(r, addr) \
    asm volatile("ldmatrix.sync.aligned.m8n8.x4.shared.b16 {%0,%1,%2,%3}, [%4];" \
        : "=r"((r)[0]), "=r"((r)[1]), "=r"((r)[2]), "=r"((r)[3]) : "r"(addr))

#define MMA(d, a, b) \
    asm volatile("mma.sync.aligned.m16n8k16.row.col.f32.f16.f16.f32 " \
        "{%0,%1,%2,%3}, {%4,%5,%6,%7}, {%8,%9}, {%0,%1,%2,%3};" \
        : "+f"((d)[0]), "+f"((d)[1]), "+f"((d)[2]), "+f"((d)[3]) \
        : "r"((a)[0]), "r"((a)[1]), "r"((a)[2]), "r"((a)[3]), "r"((b)[0]), "r"((b)[1]))

#define MMAI8(d, a, b) \
    asm volatile("mma.sync.aligned.m16n8k32.row.col.s32.s8.s8.s32 " \
        "{%0,%1,%2,%3}, {%4,%5,%6,%7}, {%8,%9}, {%0,%1,%2,%3};" \
        : "+r"((d)[0]), "+r"((d)[1]), "+r"((d)[2]), "+r"((d)[3]) \
        : "r"((a)[0]), "r"((a)[1]), "r"((a)[2]), "r"((a)[3]), "r"((b)[0]), "r"((b)[1]))

// ---------------- Conversion bodies ----------------
__device__ __forceinline__ void conv1_body(const float* __restrict__ in,
                                           h16* __restrict__ out,
                                           int R, int C, int ldin, size_t idx)
{
    int half = C >> 1;
    if (idx >= (size_t)R * half) return;
    int r = (int)(idx / half);
    int c = (int)(idx - (size_t)r * half) * 2;
    float v0 = in[(size_t)r * ldin + c];
    float v1 = in[(size_t)r * ldin + c + 1];
    *(__half2*)(out + (size_t)r * C + c) = __floats2half2_rn(v0, v1);
}

__device__ __forceinline__ void cvT1_body(const float* __restrict__ in,
                                          h16* __restrict__ out,
                                          int R, int C, int ldin, int bx, int by,
                                          int tid, float (*ts)[33])
{
    const int c0 = bx * 32, r0 = by * 32;
    const int j = tid & 31;
    #pragma unroll
    for (int q = 0; q < 4; q++) {
        int i = (tid >> 5) + q * 8;
        ts[j][i] = (c0 + j < C) ? in[(size_t)(r0 + i) * ldin + (c0 + j)] : 0.f;
    }
    __syncthreads();
    const int cl = tid >> 3, g = tid & 7;
    size_t base = (size_t)(c0 + cl) * R + r0 + g * 4;
    *(__half2*)(out + base)     = __floats2half2_rn(ts[cl][g * 4 + 0], ts[cl][g * 4 + 1]);
    *(__half2*)(out + base + 2) = __floats2half2_rn(ts[cl][g * 4 + 2], ts[cl][g * 4 + 3]);
}

__global__ void conv_x(const float* __restrict__ x, h16* __restrict__ out)
{
    conv1_body(x, out, T_SEQ, NEMBD, NEMBD, (size_t)blockIdx.x * 256 + threadIdx.x);
}
__global__ void conv_wqkv(const float* __restrict__ w, h16* __restrict__ out)
{
    __shared__ float ts[32][33];
    cvT1_body(w, out, NEMBD, LATD, LATD, blockIdx.x, blockIdx.y, threadIdx.x, ts);
}
#define NQDBLK ((QTOT / 32) * (QLOW / 32))      // 9216
#define NWOBLK ((NEMBD / 32) * (YTOT / 32))     // 16384
__global__ void conv_w2(const float* __restrict__ wqdec, h16* __restrict__ qd,
                        const float* __restrict__ wout, h16* __restrict__ wo)
{
    __shared__ float ts[32][33];
    int b = blockIdx.x;
    if (b < NQDBLK) {
        cvT1_body(wqdec, qd, QLOW, QTOT, QTOT, b % (QTOT / 32), b / (QTOT / 32), threadIdx.x, ts);
    } else {
        b -= NQDBLK;
        cvT1_body(wout, wo, YTOT, NEMBD, NEMBD, b % (NEMBD / 32), b / (NEMBD / 32), threadIdx.x, ts);
    }
}
#define NCQBLK 4096
#define NVTBLK ((KVLOW / 32) * (T_SEQ / 32))     // 1024
__global__ void conv_lat(const float* __restrict__ lat,
                         h16* __restrict__ cqh, h16* __restrict__ vt)
{
    __shared__ float ts[32][33];
    int b = blockIdx.x;
    if (b < NCQBLK) {
        conv1_body(lat + (KVLOW + ROPEHS), cqh, T_SEQ, QLOW, LATD,
                   (size_t)b * 256 + threadIdx.x);
    } else {
        b -= NCQBLK;
        cvT1_body(lat, vt, T_SEQ, KVLOW, LATD, b % (KVLOW / 32), b / (KVLOW / 32),
                  threadIdx.x, ts);
    }
}

// ---------------- Row quantization: fp16 -> int8 hi/lo + row scale ----------------
__global__ __launch_bounds__(256)
void quant_rows(const h16* __restrict__ in, int8_t* __restrict__ q1,
                int8_t* __restrict__ q2, float* __restrict__ scale, int C)
{
    __shared__ float red[8];
    __shared__ float sinv;
    const int r = blockIdx.x, tid = threadIdx.x;
    const h16* row = in + (size_t)r * C;

    float m = 0.f;
    for (int i = tid; i < C; i += 256) m = fmaxf(m, fabsf(__half2float(row[i])));
    #pragma unroll
    for (int o = 16; o; o >>= 1) m = fmaxf(m, __shfl_xor_sync(0xffffffffu, m, o));
    if ((tid & 31) == 0) red[tid >> 5] = m;
    __syncthreads();
    if (tid == 0) {
        float mm = red[0];
        #pragma unroll
        for (int i = 1; i < 8; i++) mm = fmaxf(mm, red[i]);
        scale[r] = mm / 127.f;
        sinv = (mm > 0.f) ? 127.f / mm : 0.f;
    }
    __syncthreads();
    const float inv = sinv;

    char4* o1 = (char4*)(q1 + (size_t)r * C);
    char4* o2 = (char4*)(q2 + (size_t)r * C);
    for (int i = tid * 4; i < C; i += 1024) {
        char v1[4], v2[4];
        #pragma unroll
        for (int u = 0; u < 4; u++) {
            float p = __half2float(row[i + u]) * inv;
            int a = __float2int_rn(p);
            a = max(-127, min(127, a));
            int b = __float2int_rn((p - (float)a) * 128.f);
            b = max(-127, min(127, b));
            v1[u] = (char)a; v2[u] = (char)b;
        }
        o1[i >> 2] = make_char4(v1[0], v1[1], v1[2], v1[3]);
        o2[i >> 2] = make_char4(v2[0], v2[1], v2[2], v2[3]);
    }
}

// ---------------- RoPE ----------------
__global__ void rope_pack_kernel(const float* __restrict__ lat, const float* __restrict__ qbuf,
                                 const float* __restrict__ cosT, const float* __restrict__ sinT,
                                 h16* __restrict__ kh, h16* __restrict__ qh)
{
    const int t = blockIdx.x, tid = threadIdx.x;
    __shared__ float cs[ROPEHS], sn[ROPEHS];
    if (tid < ROPEHS) {
        cs[tid] = cosT[(size_t)t * ROPEHS + tid];
        sn[tid] = sinT[(size_t)t * ROPEHS + tid];
    }
    __syncthreads();

    const float* lrow = lat + (size_t)t * LATD;
    h16* krow = kh + (size_t)t * QKHS;
    for (int p = tid; p < QKHS / 2; p += 256) {
        int e = p * 2;
        float v[2];
        #pragma unroll
        for (int u = 0; u < 2; u++) {
            int ee = e + u;
            if (ee < KVLOW) v[u] = lrow[ee];
            else {
                int i2 = ee - KVLOW;
                float xv = lrow[ee];
                v[u] = (i2 < 32) ? xv * cs[i2] - lrow[ee + 32] * sn[i2]
                                 : xv * cs[i2] + lrow[ee - 32] * sn[i2];
            }
        }
        *(__half2*)(krow + e) = __floats2half2_rn(v[0], v[1]);
    }

    const float* qrow = qbuf + (size_t)t * QTOT;
    h16* qrh = qh + (size_t)t * QTOT;
    for (int p = tid; p < QTOT / 2; p += 256) {
        int e = p * 2;
        float v[2];
        #pragma unroll
        for (int u = 0; u < 2; u++) {
            int ee = e + u;
            int hh = ee / QKHS;
            int i = ee - hh * QKHS;
            if (i < KVLOW) v[u] = qrow[ee];
            else {
                int i2 = i - KVLOW;
                float xv = qrow[ee];
                v[u] = (i2 < 32) ? xv * cs[i2] - qrow[ee + 32] * sn[i2]
                                 : xv * cs[i2] + qrow[ee - 32] * sn[i2];
            }
        }
        *(__half2*)(qrh + e) = __floats2half2_rn(v[0], v[1]);
    }
}

// ---------------- Softmax -> fp16 attn ----------------
__global__ __launch_bounds__(256)
void softmax_kernel(const float* __restrict__ scores, h16* __restrict__ attn)
{
    __shared__ float srow[T_SEQ];
    __shared__ float red[8];
    const int t = blockIdx.x, h = blockIdx.y, tid = threadIdx.x;
    const float* row = scores + ((size_t)h * T_SEQ + t) * T_SEQ;
    const int n = t + 1;

    float m = -3.4e38f;
    for (int s = tid; s < n; s += 256) { float v = row[s]; srow[s] = v; m = fmaxf(m, v); }
    #pragma unroll
    for (int o = 16; o; o >>= 1) m = fmaxf(m, __shfl_xor_sync(0xffffffffu, m, o));
    if ((tid & 31) == 0) red[tid >> 5] = m;
    __syncthreads();
    float mmax = red[0];
    #pragma unroll
    for (int i = 1; i < 8; i++) mmax = fmaxf(mmax, red[i]);
    __syncthreads();

    float sum = 0.f;
    for (int s = tid; s < n; s += 256) { float e = __expf(srow[s] - mmax); srow[s] = e; sum += e; }
    #pragma unroll
    for (int o = 16; o; o >>= 1) sum += __shfl_xor_sync(0xffffffffu, sum, o);
    if ((tid & 31) == 0) red[tid >> 5] = sum;
    __syncthreads();
    float total = 0.f;
    #pragma unroll
    for (int i = 0; i < 8; i++) total += red[i];
    const float inv = 1.f / total;

    h16* arow = attn + ((size_t)h * T_SEQ + t) * T_SEQ;
    const int kpad = ((t >> 7) + 1) << 7;
    for (int p = tid; p < (kpad >> 1); p += 256) {
        int s0 = 2 * p;
        float v0 = (s0 <= t) ? srow[s0] * inv : 0.f;
        float v1 = (s0 + 1 <= t) ? srow[s0 + 1] * inv : 0.f;
        *(__half2*)(arow + s0) = __floats2half2_rn(v0, v1);
    }
}

// ---------------- fp16 mma GEMM (attention: scores + PV) ----------------
#define TILEB  8192
#define STAGEB (2 * TILEB)
#define NSTAGE 4
#define SMEM_TOT (NSTAGE * STAGEB)  // 65536

template<int CSKIP, bool CK, int EPI>
__global__ __launch_bounds__(256, 2)
void mmagemm(const h16* __restrict__ A, const h16* __restrict__ B,
             float* __restrict__ Cf, h16* __restrict__ Ch,
             int M, int N, int K, int ldA, int ldB, int ldC,
             long sA, long sB, long sC, float alpha)
{
    extern __shared__ char smc[];
    const int bx = blockIdx.x, by = blockIdx.y, z = blockIdx.z;
    if (CSKIP && bx > by) return;

    A += (size_t)z * sA;
    B += (size_t)z * sB;

    const int Keff = CK ? min(K, (by + 1) * 128) : K;
    const int nc = Keff >> 5;
    const int tid = threadIdx.x, wid = tid >> 5, lane = tid & 31;
    const int m0 = by * 128, n0 = bx * 128;
    const uint32_t smb = smem_u32(smc);

    const int lrow = tid >> 1;
    const int lc0  = (tid & 1) * 2;
    const int lswz = (lrow >> 1) & 3;
    const uint32_t dRow = (uint32_t)(lrow * 64);
    const uint32_t d0 = dRow + (uint32_t)((lc0 ^ lswz) << 4);
    const uint32_t d1 = dRow + (uint32_t)(((lc0 + 1) ^ lswz) << 4);
    const h16* gA = A + (size_t)(m0 + lrow) * ldA + lc0 * 8;
    const h16* gB = B + (size_t)(n0 + lrow) * ldB + lc0 * 8;

#define PREFETCH(c, s) do { \
        uint32_t b_ = smb + (uint32_t)(s) * STAGEB; \
        const h16* p_ = gA + (size_t)(c) * 32; \
        CPA(b_ + d0, p_); CPA(b_ + d1, p_ + 8); \
        p_ = gB + (size_t)(c) * 32; \
        CPA(b_ + TILEB + d0, p_); CPA(b_ + TILEB + d1, p_ + 8); \
        CP_COMMIT(); \
    } while (0)

    const int wm = (wid & 1) * 64;
    const int wn = (wid >> 1) * 32;
    const int aRowL = lane & 15;
    const int aSwz = (aRowL >> 1) & 3;
    const int aCh = lane >> 4;
    const uint32_t aBase = (uint32_t)((wm + aRowL) * 64);
    const int bRowL = (lane & 7) + ((lane & 16) >> 1);
    const int bSwz = (bRowL >> 1) & 3;
    const int bCh = (lane & 8) >> 3;
    const uint32_t bBase = (uint32_t)((wn + bRowL) * 64);

    float acc[4][4][4];
    #pragma unroll
    for (int i = 0; i < 4; i++)
        #pragma unroll
        for (int j = 0; j < 4; j++)
            #pragma unroll
            for (int q = 0; q < 4; q++) acc[i][j][q] = 0.f;

    PREFETCH(0, 0);
    if (nc > 1) PREFETCH(1, 1);
    if (nc > 2) PREFETCH(2, 2);

    int st = 0;
    for (int c = 0; c < nc; ++c) {
        const int rem = nc - 1 - c;
        if (rem >= 2)      CP_WAIT(2);
        else if (rem == 1) CP_WAIT(1);
        else               CP_WAIT(0);
        __syncthreads();
        if (c + 3 < nc) {
            int ps = st + 3; if (ps >= NSTAGE) ps -= NSTAGE;
            PREFETCH(c + 3, ps);
        }

        const uint32_t base = smb + (uint32_t)st * STAGEB;
        #pragma unroll
        for (int half = 0; half < 2; half++) {
            const uint32_t aCol = (uint32_t)(((half * 2 + aCh) ^ aSwz) << 4);
            const uint32_t bCol = (uint32_t)(((half * 2 + bCh) ^ bSwz) << 4);

            uint32_t ah[4][4];
            #pragma unroll
            for (int mi = 0; mi < 4; mi++)
                LDSM4(ah[mi], base + aBase + mi * 1024 + aCol);
            uint32_t bh[4][2];
            #pragma unroll
            for (int nb = 0; nb < 2; nb++) {
                uint32_t r4[4];
                LDSM4(r4, base + TILEB + bBase + nb * 1024 + bCol);
                bh[nb * 2][0] = r4[0]; bh[nb * 2][1] = r4[1];
                bh[nb * 2 + 1][0] = r4[2]; bh[nb * 2 + 1][1] = r4[3];
            }
            #pragma unroll
            for (int mi = 0; mi < 4; mi++)
                #pragma unroll
                for (int ni = 0; ni < 4; ni++)
                    MMA(acc[mi][ni], ah[mi], bh[ni]);
        }
        if (++st == NSTAGE) st = 0;
    }
#undef PREFETCH

    const int er = lane >> 2, ec = (lane & 3) * 2;
    if (EPI == 0) {
        float* Cz = Cf + (size_t)z * sC;
        #pragma unroll
        for (int mi = 0; mi < 4; mi++) {
            const int r1 = m0 + wm + mi * 16 + er;
            #pragma unroll
            for (int ni = 0; ni < 4; ni++) {
                const int c1 = n0 + wn + ni * 8 + ec;
                if (c1 < N) {
                    float2 v0 = make_float2(acc[mi][ni][0] * alpha, acc[mi][ni][1] * alpha);
                    float2 v1 = make_float2(acc[mi][ni][2] * alpha, acc[mi][ni][3] * alpha);
                    *(float2*)(Cz + (size_t)r1 * ldC + c1) = v0;
                    *(float2*)(Cz + (size_t)(r1 + 8) * ldC + c1) = v1;
                }
            }
        }
    } else {
        h16* Cz = Ch + (size_t)z * sC;
        #pragma unroll
        for (int mi = 0; mi < 4; mi++) {
            const int r1 = m0 + wm + mi * 16 + er;
            #pragma unroll
            for (int ni = 0; ni < 4; ni++) {
                const int c1 = n0 + wn + ni * 8 + ec;
                if (c1 < N) {
                    *(__half2*)(Cz + (size_t)r1 * ldC + c1) =
                        __floats2half2_rn(acc[mi][ni][0] * alpha, acc[mi][ni][1] * alpha);
                    *(__half2*)(Cz + (size_t)(r1 + 8) * ldC + c1) =
                        __floats2half2_rn(acc[mi][ni][2] * alpha, acc[mi][ni][3] * alpha);
                }
            }
        }
    }
}

// ---------------- int8 IMMA GEMM (projections): C = sA[m]*sB[n]*(A1B1 + (A1B2+A2B1)/128) ----------------
// CTA 128x128, 512 threads, 16 warps (4m x 4n of 32x32), BK=32 (32B/row),
// 4-stage cp.async. Swizzle: 16B-chunk index ^= (row>>2)&1 (conflict-free).
#define I8TILE  4096                  // 128 rows x 32B
#define I8STAGE (4 * I8TILE)          // 16384: A1, A2, B1, B2
#define I8NST   4
#define I8SMEM  (I8NST * I8STAGE)     // 65536

__global__ __launch_bounds__(512, 1)
void i8gemm(const int8_t* __restrict__ A1, const int8_t* __restrict__ A2,
            const int8_t* __restrict__ B1, const int8_t* __restrict__ B2,
            const float* __restrict__ sA, const float* __restrict__ sB,
            float* __restrict__ Cf, int M, int N, int K, int ldC)
{
    extern __shared__ char smc[];
    const int bx = blockIdx.x, by = blockIdx.y;
    const int tid = threadIdx.x, wid = tid >> 5, lane = tid & 31;
    const int m0 = by * 128, n0 = bx * 128;
    const uint32_t smb = smem_u32(smc);
    const int nc = K >> 5;

    // loader: tile = tid>>7 (A1,A2,B1,B2), row = tid&127, both 16B halves
    const int ltile = tid >> 7, lrowq = tid & 127;
    const int8_t* gsrc;
    if (ltile == 0)      gsrc = A1 + (size_t)(m0 + lrowq) * K;
    else if (ltile == 1) gsrc = A2 + (size_t)(m0 + lrowq) * K;
    else if (ltile == 2) gsrc = B1 + (size_t)(n0 + lrowq) * K;
    else                 gsrc = B2 + (size_t)(n0 + lrowq) * K;
    const uint32_t lsw = (lrowq >> 2) & 1;
    const uint32_t ld0 = (uint32_t)(ltile * I8TILE + lrowq * 32 + ((0u ^ lsw) << 4));
    const uint32_t ld1 = (uint32_t)(ltile * I8TILE + lrowq * 32 + ((1u ^ lsw) << 4));

#define I8PRE(c, s) do { \
        uint32_t b_ = smb + (uint32_t)(s) * I8STAGE; \
        const int8_t* p_ = gsrc + (size_t)(c) * 32; \
        CPA(b_ + ld0, p_); CPA(b_ + ld1, p_ + 16); \
        CP_COMMIT(); \
    } while (0)

    // compute mapping: warp tile 32x32 (4m x 4n warps)
    const int wm = (wid & 3) * 32;
    const int wn = (wid >> 2) * 32;
    // lane j: row_local = j&15, h = j>>4; byte = row*32 + ((h ^ ((row>>2)&1))<<4)
    const int aRowL = lane & 15;
    const uint32_t aSwz = (uint32_t)((aRowL >> 2) & 1);
    const uint32_t aH = (uint32_t)(lane >> 4);
    const uint32_t aBase = (uint32_t)((wm + aRowL) * 32 + (((aH ^ aSwz)) << 4));
    const uint32_t bBase = (uint32_t)((wn + aRowL) * 32 + (((aH ^ aSwz)) << 4));
    // (same lane pattern for B: rows are n-rows)

    int acc1[2][4][4], acc2[2][4][4];
    #pragma unroll
    for (int i = 0; i < 2; i++)
        #pragma unroll
        for (int j = 0; j < 4; j++)
            #pragma unroll
            for (int q = 0; q < 4; q++) { acc1[i][j][q] = 0; acc2[i][j][q] = 0; }

    I8PRE(0, 0);
    if (nc > 1) I8PRE(1, 1);
    if (nc > 2) I8PRE(2, 2);

    int st = 0;
    for (int c = 0; c < nc; ++c) {
        const int rem = nc - 1 - c;
        if (rem >= 2)      CP_WAIT(2);
        else if (rem == 1) CP_WAIT(1);
        else               CP_WAIT(0);
        __syncthreads();
        if (c + 3 < nc) {
            int ps = st + 3; if (ps >= I8NST) ps -= I8NST;
            I8PRE(c + 3, ps);
        }

        const uint32_t base = smb + (uint32_t)st * I8STAGE;
        // A fragments: mi in {0,1}, rows wm+mi*16+... (mi*16*32 = 512 bytes)
        uint32_t a1f[2][4], a2f[2][4];
        #pragma unroll
        for (int mi = 0; mi < 2; mi++) {
            LDSM4(a1f[mi], base + aBase + mi * 512);
            LDSM4(a2f[mi], base + I8TILE + aBase + mi * 512);
        }
        // B fragments: nb in {0,1} covers n16 each -> 4 n8 tiles per split
        uint32_t b1f[4][2], b2f[4][2];
        #pragma unroll
        for (int nb = 0; nb < 2; nb++) {
            uint32_t r4[4];
            LDSM4(r4, base + 2 * I8TILE + bBase + nb * 512);
            b1f[nb * 2][0] = r4[0]; b1f[nb * 2][1] = r4[2];
            b1f[nb * 2 + 1][0] = r4[1]; b1f[nb * 2 + 1][1] = r4[3];
            LDSM4(r4, base + 3 * I8TILE + bBase + nb * 512);
            b2f[nb * 2][0] = r4[0]; b2f[nb * 2][1] = r4[2];
            b2f[nb * 2 + 1][0] = r4[1]; b2f[nb * 2 + 1][1] = r4[3];
        }
        // P1 = A1*B1 -> acc1
        #pragma unroll
        for (int mi = 0; mi < 2; mi++)
            #pragma unroll
            for (int ni = 0; ni < 4; ni++)
                MMAI8(acc1[mi][ni], a1f[mi], b1f[ni]);
        // P2 = A1*B2 -> acc2 ; P3 = A2*B1 -> acc2
        #pragma unroll
        for (int mi = 0; mi < 2; mi++)
            #pragma unroll
            for (int ni = 0; ni < 4; ni++)
                MMAI8(acc2[mi][ni], a1f[mi], b2f[ni]);
        #pragma unroll
        for (int mi = 0; mi < 2; mi++)
            #pragma unroll
            for (int ni = 0; ni < 4; ni++)
                MMAI8(acc2[mi][ni], a2f[mi], b1f[ni]);

        if (++st == I8NST) st = 0;
    }
#undef I8PRE

    // epilogue
    const int er = lane >> 2, ec = (lane & 3) * 2;
    #pragma unroll
    for (int mi = 0; mi < 2; mi++) {
        const int r1 = m0 + wm + mi * 16 + er;
        const float sa0 = sA[r1], sa1 = sA[r1 + 8];
        #pragma unroll
        for (int ni = 0; ni < 4; ni++) {
            const int c1 = n0 + wn + ni * 8 + ec;
            if (c1 < N) {
                const float sb0 = sB[c1], sb1 = sB[c1 + 1];
                float2 v0, v1;
                v0.x = sa0 * sb0 * ((float)acc1[mi][ni][0] + (float)acc2[mi][ni][0] * 0.0078125f);
                v0.y = sa0 * sb1 * ((float)acc1[mi][ni][1] + (float)acc2[mi][ni][1] * 0.0078125f);
                v1.x = sa1 * sb0 * ((float)acc1[mi][ni][2] + (float)acc2[mi][ni][2] * 0.0078125f);
                v1.y = sa1 * sb1 * ((float)acc1[mi][ni][3] + (float)acc2[mi][ni][3] * 0.0078125f);
                *(float2*)(Cf + (size_t)r1 * ldC + c1) = v0;
                *(float2*)(Cf + (size_t)(r1 + 8) * ldC + c1) = v1;
            }
        }
    }
}

// ---------------- Launch ----------------
extern "C" void kernel_launch(void* const* d_in, const int* in_sizes, int n_in,
                              void* d_out, int out_size)
{
    (void)in_sizes; (void)n_in; (void)out_size;
    const float* x     = (const float*)d_in[0];
    const float* cosT  = (const float*)d_in[1];
    const float* sinT  = (const float*)d_in[2];
    const float* Wqkv  = (const float*)d_in[3];
    const float* Wqdec = (const float*)d_in[4];
    const float* Wout  = (const float*)d_in[5];
    float* out = (float*)d_out;

    float *lat, *qbuf, *scores;
    h16 *xh, *wqkvT, *cqh, *wqdecT, *qh, *kh, *vT, *attnh, *yh, *woutT;
    int8_t *xq1, *xq2, *wkq1, *wkq2, *cqq1, *cqq2, *wdq1, *wdq2, *yq1, *yq2, *woq1, *woq2;
    float *sx, *swk, *scq, *swd, *sy, *swo;
    cudaGetSymbolAddress((void**)&lat, g_lat);
    cudaGetSymbolAddress((void**)&qbuf, g_qbuf);
    cudaGetSymbolAddress((void**)&scores, g_scores);
    cudaGetSymbolAddress((void**)&xh, g_xh);
    cudaGetSymbolAddress((void**)&wqkvT, g_wqkvT);
    cudaGetSymbolAddress((void**)&cqh, g_cqh);
    cudaGetSymbolAddress((void**)&wqdecT, g_wqdecT);
    cudaGetSymbolAddress((void**)&qh, g_qh);
    cudaGetSymbolAddress((void**)&kh, g_kh);
    cudaGetSymbolAddress((void**)&vT, g_vT);
    cudaGetSymbolAddress((void**)&attnh, g_attnh);
    cudaGetSymbolAddress((void**)&yh, g_yh);
    cudaGetSymbolAddress((void**)&woutT, g_woutT);
    cudaGetSymbolAddress((void**)&xq1, g_xq1);   cudaGetSymbolAddress((void**)&xq2, g_xq2);
    cudaGetSymbolAddress((void**)&wkq1, g_wkq1); cudaGetSymbolAddress((void**)&wkq2, g_wkq2);
    cudaGetSymbolAddress((void**)&cqq1, g_cqq1); cudaGetSymbolAddress((void**)&cqq2, g_cqq2);
    cudaGetSymbolAddress((void**)&wdq1, g_wdq1); cudaGetSymbolAddress((void**)&wdq2, g_wdq2);
    cudaGetSymbolAddress((void**)&yq1, g_yq1);   cudaGetSymbolAddress((void**)&yq2, g_yq2);
    cudaGetSymbolAddress((void**)&woq1, g_woq1); cudaGetSymbolAddress((void**)&woq2, g_woq2);
    cudaGetSymbolAddress((void**)&sx, g_sx);     cudaGetSymbolAddress((void**)&swk, g_swk);
    cudaGetSymbolAddress((void**)&scq, g_scq);   cudaGetSymbolAddress((void**)&swd, g_swd);
    cudaGetSymbolAddress((void**)&sy, g_sy);     cudaGetSymbolAddress((void**)&swo, g_swo);

    cudaFuncSetAttribute((const void*)mmagemm<1, false, 0>,
                         cudaFuncAttributeMaxDynamicSharedMemorySize, SMEM_TOT);
    cudaFuncSetAttribute((const void*)mmagemm<0, true, 1>,
                         cudaFuncAttributeMaxDynamicSharedMemorySize, SMEM_TOT);
    cudaFuncSetAttribute((const void*)i8gemm,
                         cudaFuncAttributeMaxDynamicSharedMemorySize, I8SMEM);

    const float scale = 0.04419417382415922f;   // 1/sqrt(512)

    // conversions + quantization of inputs
    conv_x<<<8192, 256>>>(x, xh);
    conv_wqkv<<<dim3(NPAD1 / 32, NEMBD / 32), 256>>>(Wqkv, wqkvT);
    conv_w2<<<NQDBLK + NWOBLK, 256>>>(Wqdec, wqdecT, Wout, woutT);
    quant_rows<<<T_SEQ, 256>>>(xh, xq1, xq2, sx, NEMBD);
    quant_rows<<<NPAD1, 256>>>(wqkvT, wkq1, wkq2, swk, NEMBD);
    quant_rows<<<QTOT, 256>>>(wqdecT, wdq1, wdq2, swd, QLOW);
    quant_rows<<<NEMBD, 256>>>(woutT, woq1, woq2, swo, YTOT);

    // G1: lat = x @ Wqkv  (int8)
    i8gemm<<<dim3(13, 16), 512, I8SMEM>>>(xq1, xq2, wkq1, wkq2, sx, swk,
                                          lat, T_SEQ, LATD, NEMBD, LATD);

    // conversions from lat + quant cq
    conv_lat<<<NCQBLK + NVTBLK, 256>>>(lat, cqh, vT);
    quant_rows<<<T_SEQ, 256>>>(cqh, cqq1, cqq2, scq, QLOW);

    // G2: qbuf = c_q @ Wqdec  (int8)
    i8gemm<<<dim3(72, 16), 512, I8SMEM>>>(cqq1, cqq2, wdq1, wdq2, scq, swd,
                                          qbuf, T_SEQ, QTOT, QLOW, QTOT);

    // RoPE
    rope_pack_kernel<<<T_SEQ, 256>>>(lat, qbuf, cosT, sinT, kh, qh);

    // scores (fp16 mma, causal tile skip)
    mmagemm<1, false, 0><<<dim3(16, 16, NHEAD), 256, SMEM_TOT>>>(
        qh, kh, scores, nullptr,
        T_SEQ, T_SEQ, QKHS, QTOT, QKHS, T_SEQ,
        (long)QKHS, 0, (long)T_SEQ * T_SEQ, scale);

    // softmax
    softmax_kernel<<<dim3(T_SEQ, NHEAD), 256>>>(scores, attnh);

    // PV (fp16 mma, K causal-truncated) -> yh fp16
    mmagemm<0, true, 1><<<dim3(4, 16, NHEAD), 256, SMEM_TOT>>>(
        attnh, vT, nullptr, yh,
        T_SEQ, KVLOW, T_SEQ, T_SEQ, T_SEQ, YTOT,
        (long)T_SEQ * T_SEQ, 0, (long)KVLOW, 1.f);

    // quant y, then G3: out = y @ Wout (int8)
    quant_rows<<<T_SEQ, 256>>>(yh, yq1, yq2, sy, YTOT);
    i8gemm<<<dim3(16, 16), 512, I8SMEM>>>(yq1, yq2, woq1, woq2, sy, swo,
                                          out, T_SEQ, NEMBD, YTOT, NEMBD);
}

// round 16
// speedup vs baseline: 3.9319x; 3.9319x over previous
#include <cuda_runtime.h>
#include <cuda_fp16.h>
#include <cstdint>

// ---------------- Problem constants ----------------
#define T_SEQ   2048
#define NEMBD   2048
#define NHEAD   16
#define KVLOW   512
#define QLOW    1024
#define ROPEHS  64
#define QKHS    576
#define LATD    1600
#define QTOT    9216
#define YTOT    8192
#define NPAD1   1664   // 1600 padded up to 13*128

typedef __half h16;

// ---------------- Scratch (device globals; no allocations allowed) ----------------
__device__ float g_lat[(size_t)T_SEQ * LATD];
__device__ float g_qbuf[(size_t)T_SEQ * QTOT];

__device__ h16 g_xh[(size_t)T_SEQ * NEMBD];
__device__ h16 g_wqkvT[(size_t)NPAD1 * NEMBD];
__device__ h16 g_cqh[(size_t)T_SEQ * QLOW];
__device__ h16 g_wqdecT[(size_t)QTOT * QLOW];
__device__ h16 g_qh[(size_t)T_SEQ * QTOT];
__device__ h16 g_kh[(size_t)T_SEQ * QKHS];
__device__ h16 g_vT[(size_t)KVLOW * T_SEQ];
__device__ h16 g_scoresh[(size_t)NHEAD * T_SEQ * T_SEQ];
__device__ h16 g_attnh[(size_t)NHEAD * T_SEQ * T_SEQ];
__device__ h16 g_yh[(size_t)T_SEQ * YTOT];
__device__ h16 g_woutT[(size_t)NEMBD * YTOT];

// ---------------- helpers ----------------
__device__ __forceinline__ uint32_t smem_u32(const void* p) {
    uint32_t a;
    asm("{ .reg .u64 t; cvta.to.shared.u64 t, %1; cvt.u32.u64 %0, t; }" : "=r"(a) : "l"(p));
    return a;
}

#define CPA(dst, src) \
    asm volatile("cp.async.cg.shared.global [%0], [%1], 16;\n" :: "r"(dst), "l"(src))
#define CP_COMMIT() asm volatile("cp.async.commit_group;\n" ::: "memory")
#define CP_WAIT(N)  asm volatile("cp.async.wait_group %0;\n" :: "n"(N) : "memory")

#define LDSM4(r, addr) \
    asm volatile("ldmatrix.sync.aligned.m8n8.x4.shared.b16 {%0,%1,%2,%3}, [%4];" \
        : "=r"((r)[0]), "=r"((r)[1]), "=r"((r)[2]), "=r"((r)[3]) : "r"(addr))

#define MMA(d, a, b) \
    asm volatile("mma.sync.aligned.m16n8k16.row.col.f32.f16.f16.f32 " \
        "{%0,%1,%2,%3}, {%4,%5,%6,%7}, {%8,%9}, {%0,%1,%2,%3};" \
        : "+f"((d)[0]), "+f"((d)[1]), "+f"((d)[2]), "+f"((d)[3]) \
        : "r"((a)[0]), "r"((a)[1]), "r"((a)[2]), "r"((a)[3]), "r"((b)[0]), "r"((b)[1]))

// ---------------- Conversion bodies ----------------
__device__ __forceinline__ void conv1_body(const float* __restrict__ in,
                                           h16* __restrict__ out,
                                           int R, int C, int ldin, size_t idx)
{
    int half = C >> 1;
    if (idx >= (size_t)R * half) return;
    int r = (int)(idx / half);
    int c = (int)(idx - (size_t)r * half) * 2;
    float v0 = in[(size_t)r * ldin + c];
    float v1 = in[(size_t)r * ldin + c + 1];
    *(__half2*)(out + (size_t)r * C + c) = __floats2half2_rn(v0, v1);
}

__device__ __forceinline__ void cvT1_body(const float* __restrict__ in,
                                          h16* __restrict__ out,
                                          int R, int C, int ldin, int bx, int by,
                                          int tid, float (*ts)[33])
{
    const int c0 = bx * 32, r0 = by * 32;
    const int j = tid & 31;
    #pragma unroll
    for (int q = 0; q < 4; q++) {
        int i = (tid >> 5) + q * 8;
        ts[j][i] = (c0 + j < C) ? in[(size_t)(r0 + i) * ldin + (c0 + j)] : 0.f;
    }
    __syncthreads();
    const int cl = tid >> 3, g = tid & 7;
    size_t base = (size_t)(c0 + cl) * R + r0 + g * 4;
    *(__half2*)(out + base)     = __floats2half2_rn(ts[cl][g * 4 + 0], ts[cl][g * 4 + 1]);
    *(__half2*)(out + base + 2) = __floats2half2_rn(ts[cl][g * 4 + 2], ts[cl][g * 4 + 3]);
}

__global__ void conv_x(const float* __restrict__ x, h16* __restrict__ out)
{
    conv1_body(x, out, T_SEQ, NEMBD, NEMBD, (size_t)blockIdx.x * 256 + threadIdx.x);
}
__global__ void conv_wqkv(const float* __restrict__ w, h16* __restrict__ out)
{
    __shared__ float ts[32][33];
    cvT1_body(w, out, NEMBD, LATD, LATD, blockIdx.x, blockIdx.y, threadIdx.x, ts);
}
#define NQDBLK ((QTOT / 32) * (QLOW / 32))      // 9216
#define NWOBLK ((NEMBD / 32) * (YTOT / 32))     // 16384
__global__ void conv_w2(const float* __restrict__ wqdec, h16* __restrict__ qd,
                        const float* __restrict__ wout, h16* __restrict__ wo)
{
    __shared__ float ts[32][33];
    int b = blockIdx.x;
    if (b < NQDBLK) {
        cvT1_body(wqdec, qd, QLOW, QTOT, QTOT, b % (QTOT / 32), b / (QTOT / 32), threadIdx.x, ts);
    } else {
        b -= NQDBLK;
        cvT1_body(wout, wo, YTOT, NEMBD, NEMBD, b % (NEMBD / 32), b / (NEMBD / 32), threadIdx.x, ts);
    }
}
#define NCQBLK 4096
#define NVTBLK ((KVLOW / 32) * (T_SEQ / 32))     // 1024
__global__ void conv_lat(const float* __restrict__ lat,
                         h16* __restrict__ cqh, h16* __restrict__ vt)
{
    __shared__ float ts[32][33];
    int b = blockIdx.x;
    if (b < NCQBLK) {
        conv1_body(lat + (KVLOW + ROPEHS), cqh, T_SEQ, QLOW, LATD,
                   (size_t)b * 256 + threadIdx.x);
    } else {
        b -= NCQBLK;
        cvT1_body(lat, vt, T_SEQ, KVLOW, LATD, b % (KVLOW / 32), b / (KVLOW / 32),
                  threadIdx.x, ts);
    }
}

// ---------------- RoPE ----------------
__global__ void rope_pack_kernel(const float* __restrict__ lat, const float* __restrict__ qbuf,
                                 const float* __restrict__ cosT, const float* __restrict__ sinT,
                                 h16* __restrict__ kh, h16* __restrict__ qh)
{
    const int t = blockIdx.x, tid = threadIdx.x;
    __shared__ float cs[ROPEHS], sn[ROPEHS];
    if (tid < ROPEHS) {
        cs[tid] = cosT[(size_t)t * ROPEHS + tid];
        sn[tid] = sinT[(size_t)t * ROPEHS + tid];
    }
    __syncthreads();

    const float* lrow = lat + (size_t)t * LATD;
    h16* krow = kh + (size_t)t * QKHS;
    for (int p = tid; p < QKHS / 2; p += 256) {
        int e = p * 2;
        float v[2];
        #pragma unroll
        for (int u = 0; u < 2; u++) {
            int ee = e + u;
            if (ee < KVLOW) v[u] = lrow[ee];
            else {
                int i2 = ee - KVLOW;
                float xv = lrow[ee];
                v[u] = (i2 < 32) ? xv * cs[i2] - lrow[ee + 32] * sn[i2]
                                 : xv * cs[i2] + lrow[ee - 32] * sn[i2];
            }
        }
        *(__half2*)(krow + e) = __floats2half2_rn(v[0], v[1]);
    }

    const float* qrow = qbuf + (size_t)t * QTOT;
    h16* qrh = qh + (size_t)t * QTOT;
    for (int p = tid; p < QTOT / 2; p += 256) {
        int e = p * 2;
        float v[2];
        #pragma unroll
        for (int u = 0; u < 2; u++) {
            int ee = e + u;
            int hh = ee / QKHS;
            int i = ee - hh * QKHS;
            if (i < KVLOW) v[u] = qrow[ee];
            else {
                int i2 = i - KVLOW;
                float xv = qrow[ee];
                v[u] = (i2 < 32) ? xv * cs[i2] - qrow[ee + 32] * sn[i2]
                                 : xv * cs[i2] + qrow[ee - 32] * sn[i2];
            }
        }
        *(__half2*)(qrh + e) = __floats2half2_rn(v[0], v[1]);
    }
}

// ---------------- Softmax (fp16 scores in) -> fp16 attn ----------------
__global__ __launch_bounds__(256)
void softmax_kernel(const h16* __restrict__ scores, h16* __restrict__ attn)
{
    __shared__ float srow[T_SEQ];
    __shared__ float red[8];
    const int t = blockIdx.x, h = blockIdx.y, tid = threadIdx.x;
    const h16* row = scores + ((size_t)h * T_SEQ + t) * T_SEQ;
    const int n = t + 1;

    float m = -3.4e38f;
    for (int s = tid; s < n; s += 256) { float v = __half2float(row[s]); srow[s] = v; m = fmaxf(m, v); }
    #pragma unroll
    for (int o = 16; o; o >>= 1) m = fmaxf(m, __shfl_xor_sync(0xffffffffu, m, o));
    if ((tid & 31) == 0) red[tid >> 5] = m;
    __syncthreads();
    float mmax = red[0];
    #pragma unroll
    for (int i = 1; i < 8; i++) mmax = fmaxf(mmax, red[i]);
    __syncthreads();

    float sum = 0.f;
    for (int s = tid; s < n; s += 256) { float e = __expf(srow[s] - mmax); srow[s] = e; sum += e; }
    #pragma unroll
    for (int o = 16; o; o >>= 1) sum += __shfl_xor_sync(0xffffffffu, sum, o);
    if ((tid & 31) == 0) red[tid >> 5] = sum;
    __syncthreads();
    float total = 0.f;
    #pragma unroll
    for (int i = 0; i < 8; i++) total += red[i];
    const float inv = 1.f / total;

    h16* arow = attn + ((size_t)h * T_SEQ + t) * T_SEQ;
    const int kpad = ((t >> 7) + 1) << 7;
    for (int p = tid; p < (kpad >> 1); p += 256) {
        int s0 = 2 * p;
        float v0 = (s0 <= t) ? srow[s0] * inv : 0.f;
        float v1 = (s0 + 1 <= t) ? srow[s0 + 1] * inv : 0.f;
        *(__half2*)(arow + s0) = __floats2half2_rn(v0, v1);
    }
}

// ---------------- fp16 mma GEMM: C = alpha * A * B^T ----------------
// CTA tile 128x128, 256 threads (8 warps, 2m x 4n of 64x32), BK=64 (128B rows,
// SW128 swizzle chunk^=(row&7)), 3-stage cp.async pipeline, 1 sync/chunk,
// 2 CTAs/SM.
#define TILEB  16384                // 128 rows x 128B
#define STAGEB (2 * TILEB)          // 32768: A, B
#define NSTAGE 3
#define SMEM_TOT (NSTAGE * STAGEB)  // 98304

template<int CSKIP, bool CK, int EPI>   // EPI: 0 -> f32 C, 1 -> fp16 C
__global__ __launch_bounds__(256, 2)
void mmagemm(const h16* __restrict__ A, const h16* __restrict__ B,
             float* __restrict__ Cf, h16* __restrict__ Ch,
             int M, int N, int K, int ldA, int ldB, int ldC,
             long sA, long sB, long sC, float alpha)
{
    extern __shared__ char smc[];
    const int bx = blockIdx.x, by = blockIdx.y, z = blockIdx.z;
    if (CSKIP && bx > by) return;   // tile fully above causal diagonal

    A += (size_t)z * sA;
    B += (size_t)z * sB;

    const int Keff = CK ? min(K, (by + 1) * 128) : K;
    const int nc = Keff >> 6;                  // 64-K chunks
    const int tid = threadIdx.x, wid = tid >> 5, lane = tid & 31;
    const int m0 = by * 128, n0 = bx * 128;
    const uint32_t smb = smem_u32(smc);

    // ---- load mapping: thread -> row tid>>1, 64B half-row (tid&1), 4 chunks of 16B ----
    const int lrow = tid >> 1;
    const int lq0  = (tid & 1) * 4;            // first 16B chunk idx (0 or 4)
    const uint32_t rsw = (uint32_t)(lrow & 7);
    uint32_t dq[4];
    #pragma unroll
    for (int q = 0; q < 4; q++)
        dq[q] = (uint32_t)(lrow * 128) + ((((uint32_t)(lq0 + q)) ^ rsw) << 4);
    const h16* gA = A + (size_t)(m0 + lrow) * ldA + lq0 * 8;
    const h16* gB = B + (size_t)(n0 + lrow) * ldB + lq0 * 8;

#define PREFETCH(c, s) do { \
        uint32_t b_ = smb + (uint32_t)(s) * STAGEB; \
        const h16* p_ = gA + (size_t)(c) * 64; \
        CPA(b_ + dq[0], p_);      CPA(b_ + dq[1], p_ + 8); \
        CPA(b_ + dq[2], p_ + 16); CPA(b_ + dq[3], p_ + 24); \
        p_ = gB + (size_t)(c) * 64; \
        CPA(b_ + TILEB + dq[0], p_);      CPA(b_ + TILEB + dq[1], p_ + 8); \
        CPA(b_ + TILEB + dq[2], p_ + 16); CPA(b_ + TILEB + dq[3], p_ + 24); \
        CP_COMMIT(); \
    } while (0)

    // ---- compute mapping: warp tile 64x32 (2m x 4n warps) ----
    const int wm = (wid & 1) * 64;
    const int wn = (wid >> 1) * 32;
    const uint32_t aSwz = (uint32_t)(lane & 7);
    const uint32_t aCh = (uint32_t)(lane >> 4);
    const uint32_t aBase = (uint32_t)((wm + (lane & 15)) * 128);
    const int bRowL = (lane & 7) + ((lane & 16) >> 1);
    const uint32_t bSwz = (uint32_t)(lane & 7);   // (bRowL & 7) == lane & 7
    const uint32_t bCh = (uint32_t)((lane & 8) >> 3);
    const uint32_t bBase = (uint32_t)((wn + bRowL) * 128);

    float acc[4][4][4];
    #pragma unroll
    for (int i = 0; i < 4; i++)
        #pragma unroll
        for (int j = 0; j < 4; j++)
            #pragma unroll
            for (int q = 0; q < 4; q++) acc[i][j][q] = 0.f;

    PREFETCH(0, 0);
    if (nc > 1) PREFETCH(1, 1);

    int st = 0;
    for (int c = 0; c < nc; ++c) {
        if (c + 1 < nc) CP_WAIT(1); else CP_WAIT(0);
        __syncthreads();
        if (c + 2 < nc) {
            int ps = st + 2; if (ps >= NSTAGE) ps -= NSTAGE;
            PREFETCH(c + 2, ps);
        }

        const uint32_t base = smb + (uint32_t)st * STAGEB;
        #pragma unroll
        for (int half = 0; half < 4; half++) {
            const uint32_t aCol = ((((uint32_t)(half * 2) + aCh) ^ aSwz) << 4);
            const uint32_t bCol = ((((uint32_t)(half * 2) + bCh) ^ bSwz) << 4);

            uint32_t ah[4][4];
            #pragma unroll
            for (int mi = 0; mi < 4; mi++)
                LDSM4(ah[mi], base + aBase + mi * 2048 + aCol);
            uint32_t bh[4][2];
            #pragma unroll
            for (int nb = 0; nb < 2; nb++) {
                uint32_t r4[4];
                LDSM4(r4, base + TILEB + bBase + nb * 2048 + bCol);
                bh[nb * 2][0] = r4[0]; bh[nb * 2][1] = r4[1];
                bh[nb * 2 + 1][0] = r4[2]; bh[nb * 2 + 1][1] = r4[3];
            }
            #pragma unroll
            for (int mi = 0; mi < 4; mi++)
                #pragma unroll
                for (int ni = 0; ni < 4; ni++)
                    MMA(acc[mi][ni], ah[mi], bh[ni]);
        }
        if (++st == NSTAGE) st = 0;
    }
#undef PREFETCH

    // ---- epilogue ----
    const int er = lane >> 2, ec = (lane & 3) * 2;
    if (EPI == 0) {
        float* Cz = Cf + (size_t)z * sC;
        #pragma unroll
        for (int mi = 0; mi < 4; mi++) {
            const int r1 = m0 + wm + mi * 16 + er;
            #pragma unroll
            for (int ni = 0; ni < 4; ni++) {
                const int c1 = n0 + wn + ni * 8 + ec;
                if (c1 < N) {
                    float2 v0 = make_float2(acc[mi][ni][0] * alpha, acc[mi][ni][1] * alpha);
                    float2 v1 = make_float2(acc[mi][ni][2] * alpha, acc[mi][ni][3] * alpha);
                    *(float2*)(Cz + (size_t)r1 * ldC + c1) = v0;
                    *(float2*)(Cz + (size_t)(r1 + 8) * ldC + c1) = v1;
                }
            }
        }
    } else {
        h16* Cz = Ch + (size_t)z * sC;
        #pragma unroll
        for (int mi = 0; mi < 4; mi++) {
            const int r1 = m0 + wm + mi * 16 + er;
            #pragma unroll
            for (int ni = 0; ni < 4; ni++) {
                const int c1 = n0 + wn + ni * 8 + ec;
                if (c1 < N) {
                    *(__half2*)(Cz + (size_t)r1 * ldC + c1) =
                        __floats2half2_rn(acc[mi][ni][0] * alpha, acc[mi][ni][1] * alpha);
                    *(__half2*)(Cz + (size_t)(r1 + 8) * ldC + c1) =
                        __floats2half2_rn(acc[mi][ni][2] * alpha, acc[mi][ni][3] * alpha);
                }
            }
        }
    }
}

// ---------------- Launch ----------------
extern "C" void kernel_launch(void* const* d_in, const int* in_sizes, int n_in,
                              void* d_out, int out_size)
{
    (void)in_sizes; (void)n_in; (void)out_size;
    const float* x     = (const float*)d_in[0];
    const float* cosT  = (const float*)d_in[1];
    const float* sinT  = (const float*)d_in[2];
    const float* Wqkv  = (const float*)d_in[3];
    const float* Wqdec = (const float*)d_in[4];
    const float* Wout  = (const float*)d_in[5];
    float* out = (float*)d_out;

    float *lat, *qbuf;
    h16 *xh, *wqkvT, *cqh, *wqdecT, *qh, *kh, *vT, *scoresh, *attnh, *yh, *woutT;
    cudaGetSymbolAddress((void**)&lat, g_lat);
    cudaGetSymbolAddress((void**)&qbuf, g_qbuf);
    cudaGetSymbolAddress((void**)&xh, g_xh);
    cudaGetSymbolAddress((void**)&wqkvT, g_wqkvT);
    cudaGetSymbolAddress((void**)&cqh, g_cqh);
    cudaGetSymbolAddress((void**)&wqdecT, g_wqdecT);
    cudaGetSymbolAddress((void**)&qh, g_qh);
    cudaGetSymbolAddress((void**)&kh, g_kh);
    cudaGetSymbolAddress((void**)&vT, g_vT);
    cudaGetSymbolAddress((void**)&scoresh, g_scoresh);
    cudaGetSymbolAddress((void**)&attnh, g_attnh);
    cudaGetSymbolAddress((void**)&yh, g_yh);
    cudaGetSymbolAddress((void**)&woutT, g_woutT);

    cudaFuncSetAttribute((const void*)mmagemm<0, false, 0>,
                         cudaFuncAttributeMaxDynamicSharedMemorySize, SMEM_TOT);
    cudaFuncSetAttribute((const void*)mmagemm<1, false, 1>,
                         cudaFuncAttributeMaxDynamicSharedMemorySize, SMEM_TOT);
    cudaFuncSetAttribute((const void*)mmagemm<0, true, 1>,
                         cudaFuncAttributeMaxDynamicSharedMemorySize, SMEM_TOT);

    const float scale = 0.04419417382415922f;   // 1/sqrt(512)

    // 0-2: input conversions
    conv_x<<<8192, 256>>>(x, xh);
    conv_wqkv<<<dim3(NPAD1 / 32, NEMBD / 32), 256>>>(Wqkv, wqkvT);
    conv_w2<<<NQDBLK + NWOBLK, 256>>>(Wqdec, wqdecT, Wout, woutT);

    // 3: G1: lat = x @ Wqkv  [2048 x 1600], K=2048
    mmagemm<0, false, 0><<<dim3(13, 16, 1), 256, SMEM_TOT>>>(
        xh, wqkvT, lat, nullptr,
        T_SEQ, LATD, NEMBD, NEMBD, NEMBD, LATD, 0, 0, 0, 1.f);

    // 4: conversions from lat (fused)
    conv_lat<<<NCQBLK + NVTBLK, 256>>>(lat, cqh, vT);

    // 5: G2: qbuf = c_q @ Wqdec  [2048 x 9216], K=1024
    mmagemm<0, false, 0><<<dim3(72, 16, 1), 256, SMEM_TOT>>>(
        cqh, wqdecT, qbuf, nullptr,
        T_SEQ, QTOT, QLOW, QLOW, QLOW, QTOT, 0, 0, 0, 1.f);

    // 6: RoPE: k, q -> fp16
    rope_pack_kernel<<<T_SEQ, 256>>>(lat, qbuf, cosT, sinT, kh, qh);

    // 7: scores[h] = scale * q_h @ k^T -> fp16, causal tile skip (K=576=9*64)
    mmagemm<1, false, 1><<<dim3(16, 16, NHEAD), 256, SMEM_TOT>>>(
        qh, kh, nullptr, scoresh,
        T_SEQ, T_SEQ, QKHS, QTOT, QKHS, T_SEQ,
        (long)QKHS, 0, (long)T_SEQ * T_SEQ, scale);

    // 8: softmax (fp16 in) -> fp16 attn
    softmax_kernel<<<dim3(T_SEQ, NHEAD), 256>>>(scoresh, attnh);

    // 9: PV: y_h = attn_h @ v (K causal-truncated to 128 mult), fp16 epilogue
    mmagemm<0, true, 1><<<dim3(4, 16, NHEAD), 256, SMEM_TOT>>>(
        attnh, vT, nullptr, yh,
        T_SEQ, KVLOW, T_SEQ, T_SEQ, T_SEQ, YTOT,
        (long)T_SEQ * T_SEQ, 0, (long)KVLOW, 1.f);

    // 10: G3: out = y @ Wout  [2048 x 2048], K=8192
    mmagemm<0, false, 0><<<dim3(16, 16, 1), 256, SMEM_TOT>>>(
        yh, woutT, out, nullptr,
        T_SEQ, NEMBD, YTOT, YTOT, YTOT, NEMBD, 0, 0, 0, 1.f);
}

// round 17
// speedup vs baseline: 4.0326x; 1.0256x over previous
#include <cuda_runtime.h>
#include <cuda_fp16.h>
#include <cstdint>

// ---------------- Problem constants ----------------
#define T_SEQ   2048
#define NEMBD   2048
#define NHEAD   16
#define KVLOW   512
#define QLOW    1024
#define ROPEHS  64
#define QKHS    576
#define LATD    1600
#define QTOT    9216
#define YTOT    8192
#define NPAD1   1664   // 1600 padded up to 13*128

typedef __half h16;

// ---------------- Scratch (device globals; no allocations allowed) ----------------
__device__ h16 g_xh[(size_t)T_SEQ * NEMBD];
__device__ h16 g_wqkvT[(size_t)NPAD1 * NEMBD];
__device__ h16 g_lath[(size_t)T_SEQ * LATD];
__device__ h16 g_wqdecT[(size_t)QTOT * QLOW];
__device__ h16 g_qh[(size_t)T_SEQ * QTOT];
__device__ h16 g_kh[(size_t)T_SEQ * QKHS];
__device__ h16 g_vT[(size_t)KVLOW * T_SEQ];
__device__ h16 g_scoresh[(size_t)NHEAD * T_SEQ * T_SEQ];
__device__ h16 g_attnh[(size_t)NHEAD * T_SEQ * T_SEQ];
__device__ h16 g_yh[(size_t)T_SEQ * YTOT];
__device__ h16 g_woutT[(size_t)NEMBD * YTOT];

// ---------------- helpers ----------------
__device__ __forceinline__ uint32_t smem_u32(const void* p) {
    uint32_t a;
    asm("{ .reg .u64 t; cvta.to.shared.u64 t, %1; cvt.u32.u64 %0, t; }" : "=r"(a) : "l"(p));
    return a;
}

#define CPA(dst, src) \
    asm volatile("cp.async.cg.shared.global [%0], [%1], 16;\n" :: "r"(dst), "l"(src))
#define CP_COMMIT() asm volatile("cp.async.commit_group;\n" ::: "memory")
#define CP_WAIT(N)  asm volatile("cp.async.wait_group %0;\n" :: "n"(N) : "memory")

#define LDSM4(r, addr) \
    asm volatile("ldmatrix.sync.aligned.m8n8.x4.shared.b16 {%0,%1,%2,%3}, [%4];" \
        : "=r"((r)[0]), "=r"((r)[1]), "=r"((r)[2]), "=r"((r)[3]) : "r"(addr))

#define MMA(d, a, b) \
    asm volatile("mma.sync.aligned.m16n8k16.row.col.f32.f16.f16.f32 " \
        "{%0,%1,%2,%3}, {%4,%5,%6,%7}, {%8,%9}, {%0,%1,%2,%3};" \
        : "+f"((d)[0]), "+f"((d)[1]), "+f"((d)[2]), "+f"((d)[3]) \
        : "r"((a)[0]), "r"((a)[1]), "r"((a)[2]), "r"((a)[3]), "r"((b)[0]), "r"((b)[1]))

// ---------------- Conversion kernels ----------------
// f32 [R][C] -> fp16 [R][C]
__device__ __forceinline__ void conv1_body(const float* __restrict__ in,
                                           h16* __restrict__ out,
                                           int R, int C, int ldin, size_t idx)
{
    int half = C >> 1;
    if (idx >= (size_t)R * half) return;
    int r = (int)(idx / half);
    int c = (int)(idx - (size_t)r * half) * 2;
    float v0 = in[(size_t)r * ldin + c];
    float v1 = in[(size_t)r * ldin + c + 1];
    *(__half2*)(out + (size_t)r * C + c) = __floats2half2_rn(v0, v1);
}

// f32 [R][C] -> transposed fp16 [Cpad][R]; rows c>=C zero.
__device__ __forceinline__ void cvT1_body(const float* __restrict__ in,
                                          h16* __restrict__ out,
                                          int R, int C, int ldin, int bx, int by,
                                          int tid, float (*ts)[33])
{
    const int c0 = bx * 32, r0 = by * 32;
    const int j = tid & 31;
    #pragma unroll
    for (int q = 0; q < 4; q++) {
        int i = (tid >> 5) + q * 8;
        ts[j][i] = (c0 + j < C) ? in[(size_t)(r0 + i) * ldin + (c0 + j)] : 0.f;
    }
    __syncthreads();
    const int cl = tid >> 3, g = tid & 7;
    size_t base = (size_t)(c0 + cl) * R + r0 + g * 4;
    *(__half2*)(out + base)     = __floats2half2_rn(ts[cl][g * 4 + 0], ts[cl][g * 4 + 1]);
    *(__half2*)(out + base + 2) = __floats2half2_rn(ts[cl][g * 4 + 2], ts[cl][g * 4 + 3]);
}

__global__ void conv_x(const float* __restrict__ x, h16* __restrict__ out)
{
    conv1_body(x, out, T_SEQ, NEMBD, NEMBD, (size_t)blockIdx.x * 256 + threadIdx.x);
}
__global__ void conv_wqkv(const float* __restrict__ w, h16* __restrict__ out)
{
    __shared__ float ts[32][33];
    cvT1_body(w, out, NEMBD, LATD, LATD, blockIdx.x, blockIdx.y, threadIdx.x, ts);
}
#define NQDBLK ((QTOT / 32) * (QLOW / 32))      // 9216
#define NWOBLK ((NEMBD / 32) * (YTOT / 32))     // 16384
__global__ void conv_w2(const float* __restrict__ wqdec, h16* __restrict__ qd,
                        const float* __restrict__ wout, h16* __restrict__ wo)
{
    __shared__ float ts[32][33];
    int b = blockIdx.x;
    if (b < NQDBLK) {
        cvT1_body(wqdec, qd, QLOW, QTOT, QTOT, b % (QTOT / 32), b / (QTOT / 32), threadIdx.x, ts);
    } else {
        b -= NQDBLK;
        cvT1_body(wout, wo, YTOT, NEMBD, NEMBD, b % (NEMBD / 32), b / (NEMBD / 32), threadIdx.x, ts);
    }
}

// fp16 transpose: vT[d][t] = lath[t][d], d in [0,512)
__global__ void conv_vt(const h16* __restrict__ lath, h16* __restrict__ vt)
{
    __shared__ float ts[32][33];
    const int tid = threadIdx.x;
    const int c0 = (blockIdx.x & 15) * 32;        // d (0..511)
    const int r0 = (blockIdx.x >> 4) * 32;        // t (0..2047)
    const int j = tid & 31;
    #pragma unroll
    for (int q = 0; q < 4; q++) {
        int i = (tid >> 5) + q * 8;
        ts[j][i] = __half2float(lath[(size_t)(r0 + i) * LATD + (c0 + j)]);
    }
    __syncthreads();
    const int cl = tid >> 3, g = tid & 7;
    size_t base = (size_t)(c0 + cl) * T_SEQ + r0 + g * 4;
    *(__half2*)(vt + base)     = __floats2half2_rn(ts[cl][g * 4 + 0], ts[cl][g * 4 + 1]);
    *(__half2*)(vt + base + 2) = __floats2half2_rn(ts[cl][g * 4 + 2], ts[cl][g * 4 + 3]);
}

// ---------------- RoPE: build kh from lath; rope qh in place ----------------
__global__ __launch_bounds__(256)
void rope2_kernel(const h16* __restrict__ lath, h16* __restrict__ kh,
                  h16* __restrict__ qh,
                  const float* __restrict__ cosT, const float* __restrict__ sinT)
{
    const int t = blockIdx.x, tid = threadIdx.x;
    __shared__ float cs[ROPEHS], sn[ROPEHS];
    if (tid < ROPEHS) {
        cs[tid] = cosT[(size_t)t * ROPEHS + tid];
        sn[tid] = sinT[(size_t)t * ROPEHS + tid];
    }
    __syncthreads();

    const h16* lrow = lath + (size_t)t * LATD;
    h16* krow = kh + (size_t)t * QKHS;
    // copy c_kv (512 dims = 256 half2)
    if (tid < 256) {
        ((__half2*)krow)[tid] = ((const __half2*)lrow)[tid];
    }
    // rope k_r: 32 pairs
    if (tid < 32) {
        float x0 = __half2float(lrow[KVLOW + tid]);
        float x1 = __half2float(lrow[KVLOW + tid + 32]);
        krow[KVLOW + tid]      = __float2half_rn(x0 * cs[tid] - x1 * sn[tid]);
        krow[KVLOW + tid + 32] = __float2half_rn(x1 * cs[tid + 32] + x0 * sn[tid + 32]);
    }
    // rope q in place: 16 heads x 32 pairs = 512 pairs
    h16* qrow = qh + (size_t)t * QTOT;
    for (int p = tid; p < NHEAD * 32; p += 256) {
        const int h = p >> 5, i = p & 31;
        h16* base = qrow + h * QKHS + KVLOW;
        float x0 = __half2float(base[i]);
        float x1 = __half2float(base[i + 32]);
        base[i]      = __float2half_rn(x0 * cs[i] - x1 * sn[i]);
        base[i + 32] = __float2half_rn(x1 * cs[i + 32] + x0 * sn[i + 32]);
    }
}

// ---------------- Softmax (fp16 scores in) -> fp16 attn ----------------
__global__ __launch_bounds__(256)
void softmax_kernel(const h16* __restrict__ scores, h16* __restrict__ attn)
{
    __shared__ float srow[T_SEQ];
    __shared__ float red[8];
    const int t = blockIdx.x, h = blockIdx.y, tid = threadIdx.x;
    const h16* row = scores + ((size_t)h * T_SEQ + t) * T_SEQ;
    const int n = t + 1;

    float m = -3.4e38f;
    for (int s = tid; s < n; s += 256) { float v = __half2float(row[s]); srow[s] = v; m = fmaxf(m, v); }
    #pragma unroll
    for (int o = 16; o; o >>= 1) m = fmaxf(m, __shfl_xor_sync(0xffffffffu, m, o));
    if ((tid & 31) == 0) red[tid >> 5] = m;
    __syncthreads();
    float mmax = red[0];
    #pragma unroll
    for (int i = 1; i < 8; i++) mmax = fmaxf(mmax, red[i]);
    __syncthreads();

    float sum = 0.f;
    for (int s = tid; s < n; s += 256) { float e = __expf(srow[s] - mmax); srow[s] = e; sum += e; }
    #pragma unroll
    for (int o = 16; o; o >>= 1) sum += __shfl_xor_sync(0xffffffffu, sum, o);
    if ((tid & 31) == 0) red[tid >> 5] = sum;
    __syncthreads();
    float total = 0.f;
    #pragma unroll
    for (int i = 0; i < 8; i++) total += red[i];
    const float inv = 1.f / total;

    h16* arow = attn + ((size_t)h * T_SEQ + t) * T_SEQ;
    const int kpad = ((t >> 7) + 1) << 7;
    for (int p = tid; p < (kpad >> 1); p += 256) {
        int s0 = 2 * p;
        float v0 = (s0 <= t) ? srow[s0] * inv : 0.f;
        float v1 = (s0 + 1 <= t) ? srow[s0 + 1] * inv : 0.f;
        *(__half2*)(arow + s0) = __floats2half2_rn(v0, v1);
    }
}

// ---------------- fp16 mma GEMM: C = alpha * A * B^T ----------------
// CTA tile 128x128, 256 threads (8 warps, 2m x 4n of 64x32), BK=64 (128B rows,
// SW128 swizzle chunk^=(row&7)), 3-stage cp.async pipeline, 2 CTAs/SM.
#define TILEB  16384
#define STAGEB (2 * TILEB)
#define NSTAGE 3
#define SMEM_TOT (NSTAGE * STAGEB)  // 98304

template<int CSKIP, bool CK, int EPI>   // EPI: 0 -> f32 C, 1 -> fp16 C
__global__ __launch_bounds__(256, 2)
void mmagemm(const h16* __restrict__ A, const h16* __restrict__ B,
             float* __restrict__ Cf, h16* __restrict__ Ch,
             int M, int N, int K, int ldA, int ldB, int ldC,
             long sA, long sB, long sC, float alpha)
{
    extern __shared__ char smc[];
    const int bx = blockIdx.x, by = blockIdx.y, z = blockIdx.z;
    if (CSKIP && bx > by) return;   // tile fully above causal diagonal

    A += (size_t)z * sA;
    B += (size_t)z * sB;

    const int Keff = CK ? min(K, (by + 1) * 128) : K;
    const int nc = Keff >> 6;                  // 64-K chunks
    const int tid = threadIdx.x, wid = tid >> 5, lane = tid & 31;
    const int m0 = by * 128, n0 = bx * 128;
    const uint32_t smb = smem_u32(smc);

    // ---- load mapping: thread -> row tid>>1, 64B half-row (tid&1), 4 chunks of 16B ----
    const int lrow = tid >> 1;
    const int lq0  = (tid & 1) * 4;
    const uint32_t rsw = (uint32_t)(lrow & 7);
    uint32_t dq[4];
    #pragma unroll
    for (int q = 0; q < 4; q++)
        dq[q] = (uint32_t)(lrow * 128) + ((((uint32_t)(lq0 + q)) ^ rsw) << 4);
    const h16* gA = A + (size_t)(m0 + lrow) * ldA + lq0 * 8;
    const h16* gB = B + (size_t)(n0 + lrow) * ldB + lq0 * 8;

#define PREFETCH(c, s) do { \
        uint32_t b_ = smb + (uint32_t)(s) * STAGEB; \
        const h16* p_ = gA + (size_t)(c) * 64; \
        CPA(b_ + dq[0], p_);      CPA(b_ + dq[1], p_ + 8); \
        CPA(b_ + dq[2], p_ + 16); CPA(b_ + dq[3], p_ + 24); \
        p_ = gB + (size_t)(c) * 64; \
        CPA(b_ + TILEB + dq[0], p_);      CPA(b_ + TILEB + dq[1], p_ + 8); \
        CPA(b_ + TILEB + dq[2], p_ + 16); CPA(b_ + TILEB + dq[3], p_ + 24); \
        CP_COMMIT(); \
    } while (0)

    // ---- compute mapping: warp tile 64x32 (2m x 4n warps) ----
    const int wm = (wid & 1) * 64;
    const int wn = (wid >> 1) * 32;
    const uint32_t aSwz = (uint32_t)(lane & 7);
    const uint32_t aCh = (uint32_t)(lane >> 4);
    const uint32_t aBase = (uint32_t)((wm + (lane & 15)) * 128);
    const int bRowL = (lane & 7) + ((lane & 16) >> 1);
    const uint32_t bSwz = (uint32_t)(lane & 7);
    const uint32_t bCh = (uint32_t)((lane & 8) >> 3);
    const uint32_t bBase = (uint32_t)((wn + bRowL) * 128);

    float acc[4][4][4];
    #pragma unroll
    for (int i = 0; i < 4; i++)
        #pragma unroll
        for (int j = 0; j < 4; j++)
            #pragma unroll
            for (int q = 0; q < 4; q++) acc[i][j][q] = 0.f;

    PREFETCH(0, 0);
    if (nc > 1) PREFETCH(1, 1);

    int st = 0;
    for (int c = 0; c < nc; ++c) {
        if (c + 1 < nc) CP_WAIT(1); else CP_WAIT(0);
        __syncthreads();
        if (c + 2 < nc) {
            int ps = st + 2; if (ps >= NSTAGE) ps -= NSTAGE;
            PREFETCH(c + 2, ps);
        }

        const uint32_t base = smb + (uint32_t)st * STAGEB;
        #pragma unroll
        for (int half = 0; half < 4; half++) {
            const uint32_t aCol = ((((uint32_t)(half * 2) + aCh) ^ aSwz) << 4);
            const uint32_t bCol = ((((uint32_t)(half * 2) + bCh) ^ bSwz) << 4);

            uint32_t ah[4][4];
            #pragma unroll
            for (int mi = 0; mi < 4; mi++)
                LDSM4(ah[mi], base + aBase + mi * 2048 + aCol);
            uint32_t bh[4][2];
            #pragma unroll
            for (int nb = 0; nb < 2; nb++) {
                uint32_t r4[4];
                LDSM4(r4, base + TILEB + bBase + nb * 2048 + bCol);
                bh[nb * 2][0] = r4[0]; bh[nb * 2][1] = r4[1];
                bh[nb * 2 + 1][0] = r4[2]; bh[nb * 2 + 1][1] = r4[3];
            }
            #pragma unroll
            for (int mi = 0; mi < 4; mi++)
                #pragma unroll
                for (int ni = 0; ni < 4; ni++)
                    MMA(acc[mi][ni], ah[mi], bh[ni]);
        }
        if (++st == NSTAGE) st = 0;
    }
#undef PREFETCH

    // ---- epilogue ----
    const int er = lane >> 2, ec = (lane & 3) * 2;
    if (EPI == 0) {
        float* Cz = Cf + (size_t)z * sC;
        #pragma unroll
        for (int mi = 0; mi < 4; mi++) {
            const int r1 = m0 + wm + mi * 16 + er;
            #pragma unroll
            for (int ni = 0; ni < 4; ni++) {
                const int c1 = n0 + wn + ni * 8 + ec;
                if (c1 < N) {
                    float2 v0 = make_float2(acc[mi][ni][0] * alpha, acc[mi][ni][1] * alpha);
                    float2 v1 = make_float2(acc[mi][ni][2] * alpha, acc[mi][ni][3] * alpha);
                    *(float2*)(Cz + (size_t)r1 * ldC + c1) = v0;
                    *(float2*)(Cz + (size_t)(r1 + 8) * ldC + c1) = v1;
                }
            }
        }
    } else {
        h16* Cz = Ch + (size_t)z * sC;
        #pragma unroll
        for (int mi = 0; mi < 4; mi++) {
            const int r1 = m0 + wm + mi * 16 + er;
            #pragma unroll
            for (int ni = 0; ni < 4; ni++) {
                const int c1 = n0 + wn + ni * 8 + ec;
                if (c1 < N) {
                    *(__half2*)(Cz + (size_t)r1 * ldC + c1) =
                        __floats2half2_rn(acc[mi][ni][0] * alpha, acc[mi][ni][1] * alpha);
                    *(__half2*)(Cz + (size_t)(r1 + 8) * ldC + c1) =
                        __floats2half2_rn(acc[mi][ni][2] * alpha, acc[mi][ni][3] * alpha);
                }
            }
        }
    }
}

// ---------------- Launch ----------------
extern "C" void kernel_launch(void* const* d_in, const int* in_sizes, int n_in,
                              void* d_out, int out_size)
{
    (void)in_sizes; (void)n_in; (void)out_size;
    const float* x     = (const float*)d_in[0];
    const float* cosT  = (const float*)d_in[1];
    const float* sinT  = (const float*)d_in[2];
    const float* Wqkv  = (const float*)d_in[3];
    const float* Wqdec = (const float*)d_in[4];
    const float* Wout  = (const float*)d_in[5];
    float* out = (float*)d_out;

    h16 *xh, *wqkvT, *lath, *wqdecT, *qh, *kh, *vT, *scoresh, *attnh, *yh, *woutT;
    cudaGetSymbolAddress((void**)&xh, g_xh);
    cudaGetSymbolAddress((void**)&wqkvT, g_wqkvT);
    cudaGetSymbolAddress((void**)&lath, g_lath);
    cudaGetSymbolAddress((void**)&wqdecT, g_wqdecT);
    cudaGetSymbolAddress((void**)&qh, g_qh);
    cudaGetSymbolAddress((void**)&kh, g_kh);
    cudaGetSymbolAddress((void**)&vT, g_vT);
    cudaGetSymbolAddress((void**)&scoresh, g_scoresh);
    cudaGetSymbolAddress((void**)&attnh, g_attnh);
    cudaGetSymbolAddress((void**)&yh, g_yh);
    cudaGetSymbolAddress((void**)&woutT, g_woutT);

    cudaFuncSetAttribute((const void*)mmagemm<0, false, 1>,
                         cudaFuncAttributeMaxDynamicSharedMemorySize, SMEM_TOT);
    cudaFuncSetAttribute((const void*)mmagemm<1, false, 1>,
                         cudaFuncAttributeMaxDynamicSharedMemorySize, SMEM_TOT);
    cudaFuncSetAttribute((const void*)mmagemm<0, true, 1>,
                         cudaFuncAttributeMaxDynamicSharedMemorySize, SMEM_TOT);
    cudaFuncSetAttribute((const void*)mmagemm<0, false, 0>,
                         cudaFuncAttributeMaxDynamicSharedMemorySize, SMEM_TOT);

    const float scale = 0.04419417382415922f;   // 1/sqrt(512)

    // 0-2: input conversions
    conv_x<<<8192, 256>>>(x, xh);
    conv_wqkv<<<dim3(NPAD1 / 32, NEMBD / 32), 256>>>(Wqkv, wqkvT);
    conv_w2<<<NQDBLK + NWOBLK, 256>>>(Wqdec, wqdecT, Wout, woutT);

    // 3: G1: lath = fp16(x @ Wqkv)  [2048 x 1600], K=2048
    mmagemm<0, false, 1><<<dim3(13, 16, 1), 256, SMEM_TOT>>>(
        xh, wqkvT, nullptr, lath,
        T_SEQ, LATD, NEMBD, NEMBD, NEMBD, LATD, 0, 0, 0, 1.f);

    // 4: vT transpose from lath (fp16)
    conv_vt<<<16 * 64, 256>>>(lath, vT);

    // 5: G2: qh = fp16(c_q @ Wqdec)  [2048 x 9216], K=1024; A aliases lath cols 576..1599
    mmagemm<0, false, 1><<<dim3(72, 16, 1), 256, SMEM_TOT>>>(
        lath + QKHS, wqdecT, nullptr, qh,
        T_SEQ, QTOT, QLOW, LATD, QLOW, QTOT, 0, 0, 0, 1.f);

    // 6: RoPE: build kh; rope qh in place
    rope2_kernel<<<T_SEQ, 256>>>(lath, kh, qh, cosT, sinT);

    // 7: scores[h] = scale * q_h @ k^T -> fp16, causal tile skip (K=576)
    mmagemm<1, false, 1><<<dim3(16, 16, NHEAD), 256, SMEM_TOT>>>(
        qh, kh, nullptr, scoresh,
        T_SEQ, T_SEQ, QKHS, QTOT, QKHS, T_SEQ,
        (long)QKHS, 0, (long)T_SEQ * T_SEQ, scale);

    // 8: softmax (fp16 in) -> fp16 attn
    softmax_kernel<<<dim3(T_SEQ, NHEAD), 256>>>(scoresh, attnh);

    // 9: PV: y_h = attn_h @ v (K causal-truncated), fp16 epilogue
    mmagemm<0, true, 1><<<dim3(4, 16, NHEAD), 256, SMEM_TOT>>>(
        attnh, vT, nullptr, yh,
        T_SEQ, KVLOW, T_SEQ, T_SEQ, T_SEQ, YTOT,
        (long)T_SEQ * T_SEQ, 0, (long)KVLOW, 1.f);

    // 10: G3: out = y @ Wout  [2048 x 2048], K=8192
    mmagemm<0, false, 0><<<dim3(16, 16, 1), 256, SMEM_TOT>>>(
        yh, woutT, out, nullptr,
        T_SEQ, NEMBD, YTOT, YTOT, YTOT, NEMBD, 0, 0, 0, 1.f);
}